// round 6
// baseline (speedup 1.0000x reference)
#include <cuda_runtime.h>
#include <cuda_pipeline.h>
#include <mma.h>
#include <math.h>

using namespace nvcuda;

#define BB   32
#define GB   8       // batches per group (A footprint 64 MB -> L2 resident)
#define NGRP (BB / GB)
#define NN   1024
#define CIN  2
#define HH   32
#define SS   2
#define CP   48      // padded channel count (34 real)
#define FP   192     // feature-buffer stride: 4 slots x 48
#define KTOT 240     // gates/final GEMM K: 5 segments x 48
#define BM   128     // hop row tile
#define BK   32      // hop k chunk (small -> deep pipeline)
#define LDA  36      // BK + 4 pad (floats)
#define NCH  (NN / BK)   // 32 chunks
#define NSTG 4       // pipeline stages

// hop smem: NSTG stages x (A 128x36 + X 32x48) floats
#define SA_ELT (BM * LDA)            // 4608 floats
#define SX_ELT (BK * CP)             // 1536 floats
#define STG_ELT (SA_ELT + SX_ELT)    // 6144 floats
#define SMEM_HOP_BYTES (NSTG * STG_ELT * 4)          // 98304 B

#define SEG_ELT (128 * CP)           // 6144 floats per feature segment tile
#define SMEM_GATES_BYTES ((KTOT * 64 + 5 * SEG_ELT) * 4)   // 184320 B
#define SMEM_FINAL_BYTES ((KTOT * 32 + 5 * SEG_ELT) * 4)   // 153600 B

// ---------------- scratch (device globals; no allocs allowed) ----------------
__device__ alignas(16) float g_X0[BB * NN * CP];
__device__ alignas(16) float g_X1[BB * NN * CP];
__device__ alignas(16) float g_F1[BB * NN * FP];   // conv1 hop outputs (4 slots)
__device__ alignas(16) float g_F2[BB * NN * FP];   // conv2 hop outputs
__device__ alignas(16) float g_U [BB * NN * HH];

// ---------------- pack X0 = [inputs | states | 0pad] ----------------
__global__ void pack_x0_kernel(const float* __restrict__ inputs,
                               const float* __restrict__ states) {
    int idx = blockIdx.x * blockDim.x + threadIdx.x;
    if (idx >= BB * NN * CP) return;
    int c  = idx % CP;
    int bn = idx / CP;
    float v = 0.0f;
    if (c < CIN)            v = inputs[bn * CIN + c];
    else if (c < CIN + HH)  v = states[bn * HH + (c - CIN)];
    g_X0[idx] = v;
}

// ---------------- hop: Y = A @ X  (tf32 WMMA, 4-stage cp.async) -------------
// mode: 0 Y1=A@X0 ; 1 Y2=A@Y1 ; 2 Z1=A@X1 ; 3 Z2=A@Z1. b0 = group batch base.
__device__ __forceinline__ void hop_load_chunk(
    float* stg, const float* __restrict__ Ag, const float* __restrict__ Xg,
    int xs, int chunk, int tid) {
    float* sA = stg;
    float* sX = stg + SA_ELT;
    const float* Ac = Ag + chunk * BK;
    const float* Xc = Xg + (size_t)(chunk * BK) * xs;
#pragma unroll
    for (int i = 0; i < 4; i++) {               // A: 128x32 = 1024 float4
        int idx = tid + i * 256;
        int r   = idx >> 3;                     // 8 float4 per row
        int c4  = idx & 7;
        __pipeline_memcpy_async(&sA[r * LDA + c4 * 4],
                                Ac + (size_t)r * NN + c4 * 4, 16);
    }
#pragma unroll
    for (int i = 0; i < 2; i++) {               // X: 32x48 = 384 float4
        int idx = tid + i * 256;
        if (idx < 384) {
            int r  = idx / 12;
            int c4 = idx % 12;
            __pipeline_memcpy_async(&sX[r * CP + c4 * 4],
                                    Xc + (size_t)r * xs + c4 * 4, 16);
        }
    }
}

__global__ __launch_bounds__(256) void hop_kernel(
    const float* __restrict__ supports, int mode, int b0) {
    extern __shared__ float smem[];

    const int tid = threadIdx.x;
    const int wid = tid >> 5;
    const int bsl = blockIdx.y;            // 0 .. GB*SS-1
    const int b   = b0 + (bsl >> 1);
    const int s   = bsl & 1;

    const float* A = supports + ((size_t)b * SS + s) * NN * NN;
    float* Fbuf = (mode < 2) ? g_F1 : g_F2;
    const float* X;
    int xs;
    if (mode == 0)      { X = g_X0 + (size_t)b * NN * CP; xs = CP; }
    else if (mode == 2) { X = g_X1 + (size_t)b * NN * CP; xs = CP; }
    else                { X = Fbuf + (size_t)b * NN * FP + s * 2 * CP; xs = FP; }
    const int slot = s * 2 + (mode & 1);
    float* Y = Fbuf + (size_t)b * NN * FP + slot * CP;

    const int row0 = blockIdx.x * BM;
    const float* Abase = A + (size_t)row0 * NN;

    wmma::fragment<wmma::accumulator, 16, 16, 8, float> acc[3];
#pragma unroll
    for (int j = 0; j < 3; j++) wmma::fill_fragment(acc[j], 0.0f);

    // prologue: NSTG-1 chunks in flight
#pragma unroll
    for (int c = 0; c < NSTG - 1; c++) {
        hop_load_chunk(smem + c * STG_ELT, Abase, X, xs, c, tid);
        __pipeline_commit();
    }

    for (int chunk = 0; chunk < NCH; chunk++) {
        const int st = chunk & (NSTG - 1);
        // prefetch chunk+NSTG-1 into the stage consumed at iter chunk-1
        if (chunk + NSTG - 1 < NCH)
            hop_load_chunk(smem + ((chunk + NSTG - 1) & (NSTG - 1)) * STG_ELT,
                           Abase, X, xs, chunk + NSTG - 1, tid);
        __pipeline_commit();                    // (possibly empty group)
        __pipeline_wait_prior(NSTG - 1);
        __syncthreads();

        const float* cA = smem + st * STG_ELT;
        const float* cX = cA + SA_ELT;
#pragma unroll
        for (int kk = 0; kk < BK; kk += 8) {
            wmma::fragment<wmma::matrix_a, 16, 16, 8, wmma::precision::tf32, wmma::row_major> af;
            wmma::load_matrix_sync(af, &cA[(wid * 16) * LDA + kk], LDA);
#pragma unroll
            for (int t = 0; t < af.num_elements; t++)
                af.x[t] = wmma::__float_to_tf32(af.x[t]);
#pragma unroll
            for (int j = 0; j < 3; j++) {
                wmma::fragment<wmma::matrix_b, 16, 16, 8, wmma::precision::tf32, wmma::row_major> bf;
                wmma::load_matrix_sync(bf, &cX[kk * CP + j * 16], CP);
#pragma unroll
                for (int t = 0; t < bf.num_elements; t++)
                    bf.x[t] = wmma::__float_to_tf32(bf.x[t]);
                wmma::mma_sync(acc[j], af, bf, acc[j]);
            }
        }
        __syncthreads();
    }

#pragma unroll
    for (int j = 0; j < 3; j++)
        wmma::store_matrix_sync(Y + (size_t)(row0 + wid * 16) * FP + j * 16,
                                acc[j], FP, wmma::mem_row_major);
}

// ---------------- gates: [128 x 240] @ [240 x 64] + sigmoid epilogue --------
// All 5 feature segments preloaded via cp.async (race-free, high MLP).
__global__ __launch_bounds__(256) void gates_kernel(
    const float* __restrict__ inputs, const float* __restrict__ states,
    const float* __restrict__ W_ru, const float* __restrict__ b_ru, int b0) {
    extern __shared__ float sm[];
    float* sW = sm;                       // 240 x 64
    float* sF = sm + KTOT * 64;           // 5 x (128 x 48)

    const int tid = threadIdx.x;
    const int wid = tid >> 5;
    const int rowBase = b0 * NN + blockIdx.x * 128;

    // issue all 5 segment loads first (async)
    for (int seg = 0; seg < 5; seg++) {
        const float* src;
        int xs;
        if (seg == 0) { src = g_X0 + (size_t)rowBase * CP; xs = CP; }
        else          { src = g_F1 + (size_t)rowBase * FP + (seg - 1) * CP; xs = FP; }
        float* dst = sF + seg * SEG_ELT;
        for (int i = tid; i < 1536; i += 256) {
            int r = i / 12, c4 = i % 12;
            __pipeline_memcpy_async(&dst[r * CP + c4 * 4],
                                    src + (size_t)r * xs + c4 * 4, 16);
        }
        __pipeline_commit();
    }

    // weights load overlaps with async segment loads
    for (int i = tid; i < KTOT * 64; i += 256) {
        int r = i >> 6, o = i & 63;
        int seg = r / CP, c = r % CP;
        float v = (c < 34) ? W_ru[(seg * 34 + c) * 64 + o] : 0.0f;
        sW[i] = wmma::__float_to_tf32(v);
    }

    wmma::fragment<wmma::accumulator, 16, 16, 8, float> acc[4];
#pragma unroll
    for (int j = 0; j < 4; j++) wmma::fill_fragment(acc[j], 0.0f);

    __pipeline_wait_prior(0);
    __syncthreads();

    for (int seg = 0; seg < 5; seg++) {
        const float* cF = sF + seg * SEG_ELT;
#pragma unroll
        for (int kk = 0; kk < CP; kk += 8) {
            wmma::fragment<wmma::matrix_a, 16, 16, 8, wmma::precision::tf32, wmma::row_major> af;
            wmma::load_matrix_sync(af, &cF[(wid * 16) * CP + kk], CP);
#pragma unroll
            for (int t = 0; t < af.num_elements; t++)
                af.x[t] = wmma::__float_to_tf32(af.x[t]);
#pragma unroll
            for (int j = 0; j < 4; j++) {
                wmma::fragment<wmma::matrix_b, 16, 16, 8, wmma::precision::tf32, wmma::row_major> bf;
                wmma::load_matrix_sync(bf, &sW[(seg * CP + kk) * 64 + j * 16], 64);
                wmma::mma_sync(acc[j], af, bf, acc[j]);
            }
        }
    }

    __syncthreads();
#pragma unroll
    for (int j = 0; j < 4; j++)
        wmma::store_matrix_sync(&sF[(wid * 16) * 64 + j * 16], acc[j], 64,
                                wmma::mem_row_major);
    __syncthreads();

    for (int idx = tid; idx < 128 * 64; idx += 256) {
        int r = idx >> 6, o = idx & 63;
        int R = rowBase + r;
        float v = sF[idx] + b_ru[o];
        float sig = 1.0f / (1.0f + expf(-v));
        if (o < HH) g_X1[(size_t)R * CP + CIN + o] = sig * states[(size_t)R * HH + o];
        else        g_U[(size_t)R * HH + (o - HH)] = sig;
    }
    for (int idx = tid; idx < 128 * 16; idx += 256) {
        int r = idx >> 4, c = idx & 15;
        int R = rowBase + r;
        if (c < 14) g_X1[(size_t)R * CP + 34 + c] = 0.0f;
        else        g_X1[(size_t)R * CP + (c - 14)] = inputs[R * CIN + (c - 14)];
    }
}

// ---------------- final: [128 x 240] @ [240 x 32] + tanh epilogue -----------
__global__ __launch_bounds__(256) void final_kernel(
    const float* __restrict__ states, const float* __restrict__ W_c,
    const float* __restrict__ b_c, float* __restrict__ out, int out_size, int b0) {
    extern __shared__ float sm[];
    float* sW = sm;                       // 240 x 32
    float* sF = sm + KTOT * 32;           // 5 x (128 x 48)

    const int tid = threadIdx.x;
    const int wid = tid >> 5;
    const int rowBase = b0 * NN + blockIdx.x * 128;
    const int total = BB * NN * HH;

    for (int seg = 0; seg < 5; seg++) {
        const float* src;
        int xs;
        if (seg == 0) { src = g_X1 + (size_t)rowBase * CP; xs = CP; }
        else          { src = g_F2 + (size_t)rowBase * FP + (seg - 1) * CP; xs = FP; }
        float* dst = sF + seg * SEG_ELT;
        for (int i = tid; i < 1536; i += 256) {
            int r = i / 12, c4 = i % 12;
            __pipeline_memcpy_async(&dst[r * CP + c4 * 4],
                                    src + (size_t)r * xs + c4 * 4, 16);
        }
        __pipeline_commit();
    }

    for (int i = tid; i < KTOT * 32; i += 256) {
        int r = i >> 5, o = i & 31;
        int seg = r / CP, c = r % CP;
        float v = (c < 34) ? W_c[(seg * 34 + c) * 32 + o] : 0.0f;
        sW[i] = wmma::__float_to_tf32(v);
    }

    wmma::fragment<wmma::accumulator, 16, 16, 8, float> acc[2];
#pragma unroll
    for (int j = 0; j < 2; j++) wmma::fill_fragment(acc[j], 0.0f);

    __pipeline_wait_prior(0);
    __syncthreads();

    for (int seg = 0; seg < 5; seg++) {
        const float* cF = sF + seg * SEG_ELT;
#pragma unroll
        for (int kk = 0; kk < CP; kk += 8) {
            wmma::fragment<wmma::matrix_a, 16, 16, 8, wmma::precision::tf32, wmma::row_major> af;
            wmma::load_matrix_sync(af, &cF[(wid * 16) * CP + kk], CP);
#pragma unroll
            for (int t = 0; t < af.num_elements; t++)
                af.x[t] = wmma::__float_to_tf32(af.x[t]);
#pragma unroll
            for (int j = 0; j < 2; j++) {
                wmma::fragment<wmma::matrix_b, 16, 16, 8, wmma::precision::tf32, wmma::row_major> bf;
                wmma::load_matrix_sync(bf, &sW[(seg * CP + kk) * 32 + j * 16], 32);
                wmma::mma_sync(acc[j], af, bf, acc[j]);
            }
        }
    }

    __syncthreads();
#pragma unroll
    for (int j = 0; j < 2; j++)
        wmma::store_matrix_sync(&sF[(wid * 16) * 32 + j * 16], acc[j], 32,
                                wmma::mem_row_major);
    __syncthreads();

    for (int idx = tid; idx < 128 * 32; idx += 256) {
        int r = idx >> 5, o = idx & 31;
        int R = rowBase + r;
        float v = sF[idx] + b_c[o];
        float c  = tanhf(v);
        float u  = g_U[(size_t)R * HH + o];
        float st = states[(size_t)R * HH + o];
        float res = u * st + (1.0f - u) * c;
        out[(size_t)R * HH + o] = res;
        if (out_size >= 2 * total)
            out[(size_t)total + (size_t)R * HH + o] = res;
    }
}

// ---------------- launch ----------------
extern "C" void kernel_launch(void* const* d_in, const int* in_sizes, int n_in,
                              void* d_out, int out_size) {
    const float* inputs   = (const float*)d_in[0];
    const float* supports = (const float*)d_in[1];
    const float* states   = (const float*)d_in[2];
    const float* W_ru     = (const float*)d_in[3];
    const float* b_ru     = (const float*)d_in[4];
    const float* W_c      = (const float*)d_in[5];
    const float* b_c      = (const float*)d_in[6];
    float* out = (float*)d_out;

    cudaFuncSetAttribute(hop_kernel,
                         cudaFuncAttributeMaxDynamicSharedMemorySize, SMEM_HOP_BYTES);
    cudaFuncSetAttribute(gates_kernel,
                         cudaFuncAttributeMaxDynamicSharedMemorySize, SMEM_GATES_BYTES);
    cudaFuncSetAttribute(final_kernel,
                         cudaFuncAttributeMaxDynamicSharedMemorySize, SMEM_FINAL_BYTES);

    pack_x0_kernel<<<(BB * NN * CP) / 256, 256>>>(inputs, states);

    dim3 hg(NN / BM, GB * SS);                       // 8 x 16 = 128 CTAs
    const int eg = (GB * NN) / 128;                  // 64 CTAs

    for (int g = 0; g < NGRP; g++) {
        const int b0 = g * GB;
        hop_kernel<<<hg, 256, SMEM_HOP_BYTES>>>(supports, 0, b0);   // Y1
        hop_kernel<<<hg, 256, SMEM_HOP_BYTES>>>(supports, 1, b0);   // Y2 (A in L2)
        gates_kernel<<<eg, 256, SMEM_GATES_BYTES>>>(inputs, states, W_ru, b_ru, b0);
        hop_kernel<<<hg, 256, SMEM_HOP_BYTES>>>(supports, 2, b0);   // Z1 (A in L2)
        hop_kernel<<<hg, 256, SMEM_HOP_BYTES>>>(supports, 3, b0);   // Z2 (A in L2)
        final_kernel<<<eg, 256, SMEM_FINAL_BYTES>>>(states, W_c, b_c, out, out_size, b0);
    }
}

// round 8
// speedup vs baseline: 1.3372x; 1.3372x over previous
#include <cuda_runtime.h>
#include <cuda_pipeline.h>
#include <mma.h>
#include <math.h>

using namespace nvcuda;

#define BB   32
#define NN   1024
#define CIN  2
#define HH   32
#define SS   2
#define CP   48      // padded channel count (34 real)
#define FP   192     // feature-buffer stride: 4 slots x 48
#define KTOT 240     // gates/final GEMM K: 5 segments x 48
#define BM   128     // hop row tile
#define BK   32      // hop k chunk (small -> deep pipeline)
#define LDA  36      // BK + 4 pad (floats)
#define NCH  (NN / BK)   // 32 chunks
#define NSTG 4       // pipeline stages

// hop smem: NSTG stages x (A 128x36 + X 32x48) floats
#define SA_ELT (BM * LDA)            // 4608 floats
#define SX_ELT (BK * CP)             // 1536 floats
#define STG_ELT (SA_ELT + SX_ELT)    // 6144 floats
#define SMEM_HOP_BYTES (NSTG * STG_ELT * 4)          // 98304 B -> 2 CTAs/SM

#define SEG_ELT (128 * CP)           // 6144 floats per feature segment tile
#define SMEM_GATES_BYTES ((KTOT * 64 + 5 * SEG_ELT) * 4)   // 184320 B
#define SMEM_FINAL_BYTES ((KTOT * 32 + 5 * SEG_ELT) * 4)   // 153600 B

// ---------------- scratch (device globals; no allocs allowed) ----------------
__device__ alignas(16) float g_X0[BB * NN * CP];
__device__ alignas(16) float g_X1[BB * NN * CP];
__device__ alignas(16) float g_F1[BB * NN * FP];   // conv1 hop outputs (4 slots)
__device__ alignas(16) float g_F2[BB * NN * FP];   // conv2 hop outputs
__device__ alignas(16) float g_U [BB * NN * HH];

// ---------------- pack X0 = [inputs | states | 0pad] ----------------
__global__ void pack_x0_kernel(const float* __restrict__ inputs,
                               const float* __restrict__ states) {
    int idx = blockIdx.x * blockDim.x + threadIdx.x;
    if (idx >= BB * NN * CP) return;
    int c  = idx % CP;
    int bn = idx / CP;
    float v = 0.0f;
    if (c < CIN)            v = inputs[bn * CIN + c];
    else if (c < CIN + HH)  v = states[bn * HH + (c - CIN)];
    g_X0[idx] = v;
}

// ---------------- hop: Y = A @ X  (tf32 WMMA, 4-stage cp.async) -------------
// mode: 0 Y1=A@X0 ; 1 Y2=A@Y1 ; 2 Z1=A@X1 ; 3 Z2=A@Z1. Full-batch grid.
__device__ __forceinline__ void hop_load_chunk(
    float* stg, const float* __restrict__ Ag, const float* __restrict__ Xg,
    int xs, int chunk, int tid) {
    float* sA = stg;
    float* sX = stg + SA_ELT;
    const float* Ac = Ag + chunk * BK;
    const float* Xc = Xg + (size_t)(chunk * BK) * xs;
#pragma unroll
    for (int i = 0; i < 4; i++) {               // A: 128x32 = 1024 float4
        int idx = tid + i * 256;
        int r   = idx >> 3;                     // 8 float4 per row
        int c4  = idx & 7;
        __pipeline_memcpy_async(&sA[r * LDA + c4 * 4],
                                Ac + (size_t)r * NN + c4 * 4, 16);
    }
#pragma unroll
    for (int i = 0; i < 2; i++) {               // X: 32x48 = 384 float4
        int idx = tid + i * 256;
        if (idx < 384) {
            int r  = idx / 12;
            int c4 = idx % 12;
            __pipeline_memcpy_async(&sX[r * CP + c4 * 4],
                                    Xc + (size_t)r * xs + c4 * 4, 16);
        }
    }
}

__global__ __launch_bounds__(256) void hop_kernel(
    const float* __restrict__ supports, int mode) {
    extern __shared__ float smem[];

    const int tid = threadIdx.x;
    const int wid = tid >> 5;
    const int bs  = blockIdx.y;            // 0 .. BB*SS-1
    const int b   = bs >> 1;
    const int s   = bs & 1;

    const float* A = supports + (size_t)bs * NN * NN;
    float* Fbuf = (mode < 2) ? g_F1 : g_F2;
    const float* X;
    int xs;
    if (mode == 0)      { X = g_X0 + (size_t)b * NN * CP; xs = CP; }
    else if (mode == 2) { X = g_X1 + (size_t)b * NN * CP; xs = CP; }
    else                { X = Fbuf + (size_t)b * NN * FP + s * 2 * CP; xs = FP; }
    const int slot = s * 2 + (mode & 1);
    float* Y = Fbuf + (size_t)b * NN * FP + slot * CP;

    const int row0 = blockIdx.x * BM;
    const float* Abase = A + (size_t)row0 * NN;

    wmma::fragment<wmma::accumulator, 16, 16, 8, float> acc[3];
#pragma unroll
    for (int j = 0; j < 3; j++) wmma::fill_fragment(acc[j], 0.0f);

    // prologue: NSTG-1 chunks in flight
#pragma unroll
    for (int c = 0; c < NSTG - 1; c++) {
        hop_load_chunk(smem + c * STG_ELT, Abase, X, xs, c, tid);
        __pipeline_commit();
    }

    for (int chunk = 0; chunk < NCH; chunk++) {
        const int st = chunk & (NSTG - 1);
        // prefetch chunk+NSTG-1 into the stage consumed at iter chunk-1
        if (chunk + NSTG - 1 < NCH)
            hop_load_chunk(smem + ((chunk + NSTG - 1) & (NSTG - 1)) * STG_ELT,
                           Abase, X, xs, chunk + NSTG - 1, tid);
        __pipeline_commit();                    // (possibly empty group)
        __pipeline_wait_prior(NSTG - 1);
        __syncthreads();

        const float* cA = smem + st * STG_ELT;
        const float* cX = cA + SA_ELT;
#pragma unroll
        for (int kk = 0; kk < BK; kk += 8) {
            wmma::fragment<wmma::matrix_a, 16, 16, 8, wmma::precision::tf32, wmma::row_major> af;
            wmma::load_matrix_sync(af, &cA[(wid * 16) * LDA + kk], LDA);
#pragma unroll
            for (int t = 0; t < af.num_elements; t++)
                af.x[t] = wmma::__float_to_tf32(af.x[t]);
#pragma unroll
            for (int j = 0; j < 3; j++) {
                wmma::fragment<wmma::matrix_b, 16, 16, 8, wmma::precision::tf32, wmma::row_major> bf;
                wmma::load_matrix_sync(bf, &cX[kk * CP + j * 16], CP);
#pragma unroll
                for (int t = 0; t < bf.num_elements; t++)
                    bf.x[t] = wmma::__float_to_tf32(bf.x[t]);
                wmma::mma_sync(acc[j], af, bf, acc[j]);
            }
        }
        __syncthreads();
    }

#pragma unroll
    for (int j = 0; j < 3; j++)
        wmma::store_matrix_sync(Y + (size_t)(row0 + wid * 16) * FP + j * 16,
                                acc[j], FP, wmma::mem_row_major);
}

// ---------------- gates: [128 x 240] @ [240 x 64] + sigmoid epilogue --------
// All 5 feature segments preloaded via cp.async (race-free, high MLP).
__global__ __launch_bounds__(256) void gates_kernel(
    const float* __restrict__ inputs, const float* __restrict__ states,
    const float* __restrict__ W_ru, const float* __restrict__ b_ru) {
    extern __shared__ float sm[];
    float* sW = sm;                       // 240 x 64
    float* sF = sm + KTOT * 64;           // 5 x (128 x 48)

    const int tid = threadIdx.x;
    const int wid = tid >> 5;
    const int rowBase = blockIdx.x * 128;

    // issue all 5 segment loads first (async)
    for (int seg = 0; seg < 5; seg++) {
        const float* src;
        int xs;
        if (seg == 0) { src = g_X0 + (size_t)rowBase * CP; xs = CP; }
        else          { src = g_F1 + (size_t)rowBase * FP + (seg - 1) * CP; xs = FP; }
        float* dst = sF + seg * SEG_ELT;
        for (int i = tid; i < 1536; i += 256) {
            int r = i / 12, c4 = i % 12;
            __pipeline_memcpy_async(&dst[r * CP + c4 * 4],
                                    src + (size_t)r * xs + c4 * 4, 16);
        }
        __pipeline_commit();
    }

    // weights load overlaps with async segment loads
    for (int i = tid; i < KTOT * 64; i += 256) {
        int r = i >> 6, o = i & 63;
        int seg = r / CP, c = r % CP;
        float v = (c < 34) ? W_ru[(seg * 34 + c) * 64 + o] : 0.0f;
        sW[i] = wmma::__float_to_tf32(v);
    }

    wmma::fragment<wmma::accumulator, 16, 16, 8, float> acc[4];
#pragma unroll
    for (int j = 0; j < 4; j++) wmma::fill_fragment(acc[j], 0.0f);

    __pipeline_wait_prior(0);
    __syncthreads();

    for (int seg = 0; seg < 5; seg++) {
        const float* cF = sF + seg * SEG_ELT;
#pragma unroll
        for (int kk = 0; kk < CP; kk += 8) {
            wmma::fragment<wmma::matrix_a, 16, 16, 8, wmma::precision::tf32, wmma::row_major> af;
            wmma::load_matrix_sync(af, &cF[(wid * 16) * CP + kk], CP);
#pragma unroll
            for (int t = 0; t < af.num_elements; t++)
                af.x[t] = wmma::__float_to_tf32(af.x[t]);
#pragma unroll
            for (int j = 0; j < 4; j++) {
                wmma::fragment<wmma::matrix_b, 16, 16, 8, wmma::precision::tf32, wmma::row_major> bf;
                wmma::load_matrix_sync(bf, &sW[(seg * CP + kk) * 64 + j * 16], 64);
                wmma::mma_sync(acc[j], af, bf, acc[j]);
            }
        }
    }

    __syncthreads();
#pragma unroll
    for (int j = 0; j < 4; j++)
        wmma::store_matrix_sync(&sF[(wid * 16) * 64 + j * 16], acc[j], 64,
                                wmma::mem_row_major);
    __syncthreads();

    for (int idx = tid; idx < 128 * 64; idx += 256) {
        int r = idx >> 6, o = idx & 63;
        int R = rowBase + r;
        float v = sF[idx] + b_ru[o];
        float sig = 1.0f / (1.0f + expf(-v));
        if (o < HH) g_X1[(size_t)R * CP + CIN + o] = sig * states[(size_t)R * HH + o];
        else        g_U[(size_t)R * HH + (o - HH)] = sig;
    }
    for (int idx = tid; idx < 128 * 16; idx += 256) {
        int r = idx >> 4, c = idx & 15;
        int R = rowBase + r;
        if (c < 14) g_X1[(size_t)R * CP + 34 + c] = 0.0f;
        else        g_X1[(size_t)R * CP + (c - 14)] = inputs[R * CIN + (c - 14)];
    }
}

// ---------------- final: [128 x 240] @ [240 x 32] + tanh epilogue -----------
__global__ __launch_bounds__(256) void final_kernel(
    const float* __restrict__ states, const float* __restrict__ W_c,
    const float* __restrict__ b_c, float* __restrict__ out, int out_size) {
    extern __shared__ float sm[];
    float* sW = sm;                       // 240 x 32
    float* sF = sm + KTOT * 32;           // 5 x (128 x 48)

    const int tid = threadIdx.x;
    const int wid = tid >> 5;
    const int rowBase = blockIdx.x * 128;
    const int total = BB * NN * HH;

    for (int seg = 0; seg < 5; seg++) {
        const float* src;
        int xs;
        if (seg == 0) { src = g_X1 + (size_t)rowBase * CP; xs = CP; }
        else          { src = g_F2 + (size_t)rowBase * FP + (seg - 1) * CP; xs = FP; }
        float* dst = sF + seg * SEG_ELT;
        for (int i = tid; i < 1536; i += 256) {
            int r = i / 12, c4 = i % 12;
            __pipeline_memcpy_async(&dst[r * CP + c4 * 4],
                                    src + (size_t)r * xs + c4 * 4, 16);
        }
        __pipeline_commit();
    }

    for (int i = tid; i < KTOT * 32; i += 256) {
        int r = i >> 5, o = i & 31;
        int seg = r / CP, c = r % CP;
        float v = (c < 34) ? W_c[(seg * 34 + c) * 32 + o] : 0.0f;
        sW[i] = wmma::__float_to_tf32(v);
    }

    wmma::fragment<wmma::accumulator, 16, 16, 8, float> acc[2];
#pragma unroll
    for (int j = 0; j < 2; j++) wmma::fill_fragment(acc[j], 0.0f);

    __pipeline_wait_prior(0);
    __syncthreads();

    for (int seg = 0; seg < 5; seg++) {
        const float* cF = sF + seg * SEG_ELT;
#pragma unroll
        for (int kk = 0; kk < CP; kk += 8) {
            wmma::fragment<wmma::matrix_a, 16, 16, 8, wmma::precision::tf32, wmma::row_major> af;
            wmma::load_matrix_sync(af, &cF[(wid * 16) * CP + kk], CP);
#pragma unroll
            for (int t = 0; t < af.num_elements; t++)
                af.x[t] = wmma::__float_to_tf32(af.x[t]);
#pragma unroll
            for (int j = 0; j < 2; j++) {
                wmma::fragment<wmma::matrix_b, 16, 16, 8, wmma::precision::tf32, wmma::row_major> bf;
                wmma::load_matrix_sync(bf, &sW[(seg * CP + kk) * 32 + j * 16], 32);
                wmma::mma_sync(acc[j], af, bf, acc[j]);
            }
        }
    }

    __syncthreads();
#pragma unroll
    for (int j = 0; j < 2; j++)
        wmma::store_matrix_sync(&sF[(wid * 16) * 32 + j * 16], acc[j], 32,
                                wmma::mem_row_major);
    __syncthreads();

    for (int idx = tid; idx < 128 * 32; idx += 256) {
        int r = idx >> 5, o = idx & 31;
        int R = rowBase + r;
        float v = sF[idx] + b_c[o];
        float c  = tanhf(v);
        float u  = g_U[(size_t)R * HH + o];
        float st = states[(size_t)R * HH + o];
        float res = u * st + (1.0f - u) * c;
        out[(size_t)R * HH + o] = res;
        if (out_size >= 2 * total)
            out[(size_t)total + (size_t)R * HH + o] = res;
    }
}

// ---------------- launch ----------------
extern "C" void kernel_launch(void* const* d_in, const int* in_sizes, int n_in,
                              void* d_out, int out_size) {
    const float* inputs   = (const float*)d_in[0];
    const float* supports = (const float*)d_in[1];
    const float* states   = (const float*)d_in[2];
    const float* W_ru     = (const float*)d_in[3];
    const float* b_ru     = (const float*)d_in[4];
    const float* W_c      = (const float*)d_in[5];
    const float* b_c      = (const float*)d_in[6];
    float* out = (float*)d_out;

    cudaFuncSetAttribute(hop_kernel,
                         cudaFuncAttributeMaxDynamicSharedMemorySize, SMEM_HOP_BYTES);
    cudaFuncSetAttribute(gates_kernel,
                         cudaFuncAttributeMaxDynamicSharedMemorySize, SMEM_GATES_BYTES);
    cudaFuncSetAttribute(final_kernel,
                         cudaFuncAttributeMaxDynamicSharedMemorySize, SMEM_FINAL_BYTES);

    pack_x0_kernel<<<(BB * NN * CP) / 256, 256>>>(inputs, states);

    dim3 hg(NN / BM, BB * SS);                       // 8 x 64 = 512 CTAs (full chip)
    const int eg = (BB * NN) / 128;                  // 256 CTAs

    hop_kernel<<<hg, 256, SMEM_HOP_BYTES>>>(supports, 0);   // Y1 = A @ X0
    hop_kernel<<<hg, 256, SMEM_HOP_BYTES>>>(supports, 1);   // Y2 = A @ Y1
    gates_kernel<<<eg, 256, SMEM_GATES_BYTES>>>(inputs, states, W_ru, b_ru);
    hop_kernel<<<hg, 256, SMEM_HOP_BYTES>>>(supports, 2);   // Z1 = A @ X1
    hop_kernel<<<hg, 256, SMEM_HOP_BYTES>>>(supports, 3);   // Z2 = A @ Z1
    final_kernel<<<eg, 256, SMEM_FINAL_BYTES>>>(states, W_c, b_c, out, out_size);
}